// round 4
// baseline (speedup 1.0000x reference)
#include <cuda_runtime.h>

#define H        1024
#define S        32768
#define THREADS  256
#define WARPS    (THREADS / 32)
#define GRID     444                          // 148 SMs * 3 CTAs, one wave
#define N_WARPS  (GRID * WARPS)               // 3552 warps
#define VEC      8                            // 8 x float4 per thread = 32 cols

__global__ void zero_out_kernel(float* __restrict__ out) {
    int i = blockIdx.x * blockDim.x + threadIdx.x;
    if (i < H) out[i] = 0.0f;
}

__global__ __launch_bounds__(THREADS, 3)
void bahdanau_cos_kernel(const float* __restrict__ query,
                         const float* __restrict__ keys,
                         float* __restrict__ out) {
    __shared__ float s_q[H];
    __shared__ float s_ctx[H];

    const int tid  = threadIdx.x;
    const int lane = tid & 31;
    const int warp = tid >> 5;

    for (int i = tid; i < H; i += THREADS) {
        s_q[i]   = query[i];
        s_ctx[i] = 0.0f;
    }
    __syncthreads();

    const float4* s_q4 = reinterpret_cast<const float4*>(s_q);

    // each warp computes ||q||^-1 from smem (cheap, no extra block sync)
    float qss = 0.0f;
#pragma unroll
    for (int j = 0; j < VEC; j++) {
        float4 q = s_q4[j * 32 + lane];
        qss += q.x * q.x + q.y * q.y + q.z * q.z + q.w * q.w;
    }
#pragma unroll
    for (int o = 16; o > 0; o >>= 1)
        qss += __shfl_xor_sync(0xFFFFFFFFu, qss, o);
    const float inv_qn = rsqrtf(qss);

    float acc[VEC * 4];
#pragma unroll
    for (int i = 0; i < VEC * 4; i++) acc[i] = 0.0f;

    // round-robin (grid-stride) rows: all warps sweep one moving window
    // of the keys matrix together -> DRAM row-buffer locality.
    const int gw = blockIdx.x * WARPS + warp;

    for (int row = gw; row < S; row += N_WARPS) {
        const float4* kr = reinterpret_cast<const float4*>(keys + (size_t)row * H);

        float4 kv[VEC];
        float dot = 0.0f, kss = 0.0f;
#pragma unroll
        for (int j = 0; j < VEC; j++)
            kv[j] = kr[j * 32 + lane];
#pragma unroll
        for (int j = 0; j < VEC; j++) {
            float4 q = s_q4[j * 32 + lane];
            dot += q.x * kv[j].x + q.y * kv[j].y + q.z * kv[j].z + q.w * kv[j].w;
            kss += kv[j].x * kv[j].x + kv[j].y * kv[j].y
                 + kv[j].z * kv[j].z + kv[j].w * kv[j].w;
        }
#pragma unroll
        for (int o = 16; o > 0; o >>= 1) {
            dot += __shfl_xor_sync(0xFFFFFFFFu, dot, o);
            kss += __shfl_xor_sync(0xFFFFFFFFu, kss, o);
        }
        const float score = dot * inv_qn * rsqrtf(kss);
#pragma unroll
        for (int j = 0; j < VEC; j++) {
            acc[j * 4 + 0] += score * kv[j].x;
            acc[j * 4 + 1] += score * kv[j].y;
            acc[j * 4 + 2] += score * kv[j].z;
            acc[j * 4 + 3] += score * kv[j].w;
        }
    }

    __syncthreads();   // s_ctx zero visible to all

    // warp partials -> shared context (spread addresses, low contention)
#pragma unroll
    for (int j = 0; j < VEC; j++) {
        const int col = j * 128 + lane * 4;
        atomicAdd(&s_ctx[col + 0], acc[j * 4 + 0]);
        atomicAdd(&s_ctx[col + 1], acc[j * 4 + 1]);
        atomicAdd(&s_ctx[col + 2], acc[j * 4 + 2]);
        atomicAdd(&s_ctx[col + 3], acc[j * 4 + 3]);
    }
    __syncthreads();

    // block partial -> global output
    for (int i = tid; i < H; i += THREADS)
        atomicAdd(&out[i], s_ctx[i]);
}

extern "C" void kernel_launch(void* const* d_in, const int* in_sizes, int n_in,
                              void* d_out, int out_size) {
    const float* query = (const float*)d_in[0];   // [1,1024]
    const float* keys  = (const float*)d_in[1];   // [32768,1024]
    float* out = (float*)d_out;                   // [1,1024]

    zero_out_kernel<<<4, 256>>>(out);
    bahdanau_cos_kernel<<<GRID, THREADS>>>(query, keys, out);
}

// round 6
// speedup vs baseline: 1.3471x; 1.3471x over previous
#include <cuda_runtime.h>

#define H        1024
#define S        32768
#define THREADS  256
#define WARPS    (THREADS / 32)
#define GRID     296                          // 148 SMs * 2 CTAs, balanced wave
#define N_WARPS  (GRID * WARPS)               // 2368 warps
#define VEC      8                            // 8 x float4 per thread = 32 cols

__global__ void zero_out_kernel(float* __restrict__ out) {
    int i = blockIdx.x * blockDim.x + threadIdx.x;
    if (i < H) out[i] = 0.0f;
}

__global__ __launch_bounds__(THREADS, 2)
void bahdanau_cos_kernel(const float* __restrict__ query,
                         const float* __restrict__ keys,
                         float* __restrict__ out) {
    __shared__ float s_ctx[H];

    const int tid  = threadIdx.x;
    const int lane = tid & 31;
    const int warp = tid >> 5;

    for (int i = tid; i < H; i += THREADS) s_ctx[i] = 0.0f;

    // q lives in registers (32 regs) — NOT shared memory.
    float4 qv[VEC];
    float qss = 0.0f;
    const float4* q4 = reinterpret_cast<const float4*>(query);
#pragma unroll
    for (int j = 0; j < VEC; j++) {
        qv[j] = __ldg(&q4[j * 32 + lane]);
        qss += qv[j].x * qv[j].x + qv[j].y * qv[j].y
             + qv[j].z * qv[j].z + qv[j].w * qv[j].w;
    }
#pragma unroll
    for (int o = 16; o > 0; o >>= 1)
        qss += __shfl_xor_sync(0xFFFFFFFFu, qss, o);
    const float inv_qn = rsqrtf(qss);

    float acc[VEC * 4];
#pragma unroll
    for (int i = 0; i < VEC * 4; i++) acc[i] = 0.0f;

    const int gw = blockIdx.x * WARPS + warp;

    // Round-robin rows (all warps sweep one moving window: DRAM locality).
    // kv is TRANSIENT: consumed into dot/kss immediately, then the row is
    // re-read from L1 for the accumulation. This frees 32 registers so
    // ptxas can hoist row i+1's global loads across row i's shuffle chain.
#pragma unroll 2
    for (int row = gw; row < S; row += N_WARPS) {
        const float4* kr = reinterpret_cast<const float4*>(keys + (size_t)row * H);

        float dot = 0.0f, kss = 0.0f;
#pragma unroll
        for (int j = 0; j < VEC; j++) {
            const float4 k = kr[j * 32 + lane];        // DRAM/L2 read
            dot += qv[j].x * k.x + qv[j].y * k.y + qv[j].z * k.z + qv[j].w * k.w;
            kss += k.x * k.x + k.y * k.y + k.z * k.z + k.w * k.w;
        }
#pragma unroll
        for (int o = 16; o > 0; o >>= 1) {
            dot += __shfl_xor_sync(0xFFFFFFFFu, dot, o);
            kss += __shfl_xor_sync(0xFFFFFFFFu, kss, o);
        }
        const float score = dot * inv_qn * rsqrtf(kss);

#pragma unroll
        for (int j = 0; j < VEC; j++) {
            const float4 k = __ldca(&kr[j * 32 + lane]);   // L1 hit re-read
            acc[j * 4 + 0] += score * k.x;
            acc[j * 4 + 1] += score * k.y;
            acc[j * 4 + 2] += score * k.z;
            acc[j * 4 + 3] += score * k.w;
        }
    }

    __syncthreads();   // s_ctx zero visible to all

    // warp partials -> shared context (spread addresses, low contention)
#pragma unroll
    for (int j = 0; j < VEC; j++) {
        const int col = j * 128 + lane * 4;
        atomicAdd(&s_ctx[col + 0], acc[j * 4 + 0]);
        atomicAdd(&s_ctx[col + 1], acc[j * 4 + 1]);
        atomicAdd(&s_ctx[col + 2], acc[j * 4 + 2]);
        atomicAdd(&s_ctx[col + 3], acc[j * 4 + 3]);
    }
    __syncthreads();

    // block partial -> global output
    for (int i = tid; i < H; i += THREADS)
        atomicAdd(&out[i], s_ctx[i]);
}

extern "C" void kernel_launch(void* const* d_in, const int* in_sizes, int n_in,
                              void* d_out, int out_size) {
    const float* query = (const float*)d_in[0];   // [1,1024]
    const float* keys  = (const float*)d_in[1];   // [32768,1024]
    float* out = (float*)d_out;                   // [1,1024]

    zero_out_kernel<<<4, 256>>>(out);
    bahdanau_cos_kernel<<<GRID, THREADS>>>(query, keys, out);
}